// round 3
// baseline (speedup 1.0000x reference)
#include <cuda_runtime.h>
#include <cstdint>

#define Bt   128
#define Tt   512
#define Et   256
#define Ht   512
#define VCt  64
#define VPt  128
#define NCTA 128
#define CSZ  4
#define CCOLS 16   // columns per cluster
#define KSL  128   // K-slice per CTA

typedef unsigned long long ull;

// ---------------- persistent device scratch ----------------
__device__ float g_P[VCt * Ht];
__device__ float g_h0[2][Ht * Bt];
__device__ float g_h1[2][Ht * Bt];
__device__ float g_ysT[(size_t)Tt * Ht * Bt];
__device__ unsigned g_count = 0;
__device__ unsigned g_sense = 0;

// ---------------- f32x2 helpers ----------------
__device__ __forceinline__ ull pk(float a, float b) {
  ull r; asm("mov.b64 %0, {%1,%2};" : "=l"(r) : "f"(a), "f"(b)); return r;
}
__device__ __forceinline__ ull fma2(ull a, ull b, ull c) {
  ull d; asm("fma.rn.f32x2 %0, %1, %2, %3;" : "=l"(d) : "l"(a), "l"(b), "l"(c));
  return d;
}
__device__ __forceinline__ ull add2(ull a, ull b) {
  ull d; asm("add.rn.f32x2 %0, %1, %2;" : "=l"(d) : "l"(a), "l"(b)); return d;
}
__device__ __forceinline__ float2 upk(ull v) {
  float2 f; asm("mov.b64 {%0,%1}, %2;" : "=f"(f.x), "=f"(f.y) : "l"(v)); return f;
}
__device__ __forceinline__ uint32_t smem_u32(const void* p) {
  uint32_t a;
  asm("{ .reg .u64 t; cvta.to.shared.u64 t, %1; cvt.u32.u64 %0, t; }"
      : "=r"(a) : "l"(p));
  return a;
}
__device__ __forceinline__ void st_mail(uint32_t mail_base, int dst_rank,
                                        int off_ull, ull v) {
  uint32_t a = mail_base + (uint32_t)off_ull * 8u;
  uint32_t r;
  asm volatile("mapa.shared::cluster.u32 %0, %1, %2;" : "=r"(r) : "r"(a), "r"(dst_rank));
  asm volatile("st.shared::cluster.u64 [%0], %1;" :: "r"(r), "l"(v));
}
#define CSYNC()                                                         \
  do {                                                                  \
    asm volatile("barrier.cluster.arrive.aligned;" ::: "memory");       \
    asm volatile("barrier.cluster.wait.aligned;" ::: "memory");         \
  } while (0)

// ---------------- kernel 1: P = emb_table @ W_xh0 + b_xh0 ----------------
__global__ __launch_bounds__(128) void proj_kernel(
    const float* __restrict__ emb, const float* __restrict__ Wxh0,
    const float* __restrict__ bxh0) {
  __shared__ float esh[Et];
  int v = blockIdx.x;
  for (int i = threadIdx.x; i < Et; i += 128) esh[i] = emb[v * Et + i];
  __syncthreads();
  int j = threadIdx.x + blockIdx.y * 128;
  float s = bxh0[j];
#pragma unroll 8
  for (int e = 0; e < Et; ++e) s = fmaf(esh[e], Wxh0[e * Ht + j], s);
  g_P[v * Ht + j] = s;
}

// ---------------- kernel 2: persistent recurrent kernel ----------------
// 32 clusters x 4 CTAs. Cluster owns 16 columns; CTA rank r handles
// K-slice [r*128, r*128+128) for all 16 cols, finalizes cols j0 = jc0+4r..+3.
__global__ __launch_bounds__(256, 1) __cluster_dims__(CSZ, 1, 1)
void rec_kernel(const int* __restrict__ src, const int* __restrict__ lens,
                const float* __restrict__ Whh0, const float* __restrict__ Wxh1,
                const float* __restrict__ bxh1, const float* __restrict__ Whh1) {
  extern __shared__ char dsm[];
  ull* Wp0 = (ull*)dsm;              // [128k][16c] packed {w,w}   16 KB
  ull* Wp1 = Wp0 + 2048;             // 16 KB
  ull* Wp2 = Wp1 + 2048;             // 16 KB
  ull* red2 = Wp2 + 2048;            // [8 s][16 c][64 pr]         64 KB
  ull* mail2 = red2 + 8192;          // [4 src][4 jj][64 pr]        8 KB
  float* Psh = (float*)(mail2 + 1024);  // [64 v][4 jj]              1 KB

  __shared__ int srcsh[Bt];
  __shared__ int lensh[Bt];
  __shared__ float bsh[4];
  __shared__ unsigned s_sense;

  const int tid = threadIdx.x;
  int rank;
  asm("mov.u32 %0, %%cluster_ctarank;" : "=r"(rank));
  const int jc0 = (blockIdx.x >> 2) * CCOLS;
  const int j0 = jc0 + rank * 4;
  const int kbase = rank * KSL;
  const uint32_t mail_base = smem_u32(mail2);

  // weights (packed broadcast pairs)
  for (int i = tid; i < 2048; i += 256) {
    int k = i >> 4, c = i & 15;
    float w0 = Whh0[(kbase + k) * Ht + jc0 + c];
    float w1 = Wxh1[(kbase + k) * Ht + jc0 + c];
    float w2 = Whh1[(kbase + k) * Ht + jc0 + c];
    Wp0[i] = pk(w0, w0);
    Wp1[i] = pk(w1, w1);
    Wp2[i] = pk(w2, w2);
  }
  for (int i = tid; i < VCt * 4; i += 256) {
    int v = i >> 2, jj = i & 3;
    Psh[i] = g_P[v * Ht + j0 + jj];
  }
  if (tid < Bt) lensh[tid] = lens[tid];
  if (tid < 4) bsh[tid] = bxh1[j0 + tid];
  for (int i = tid; i < 512; i += 256) {
    int jj = i >> 7, b = i & 127;
    g_h0[1][(j0 + jj) * Bt + b] = 0.f;
    g_h1[1][(j0 + jj) * Bt + b] = 0.f;
  }
  if (tid == 0) s_sense = *(volatile unsigned*)&g_sense;
  __syncthreads();

#define GBAR()                                              \
  do {                                                      \
    __syncthreads();                                        \
    if (tid == 0) {                                         \
      unsigned ns = s_sense ^ 1u;                           \
      __threadfence();                                      \
      unsigned old = atomicAdd(&g_count, 1u);               \
      if (old == (unsigned)(NCTA - 1)) {                    \
        g_count = 0u;                                       \
        __threadfence();                                    \
        *(volatile unsigned*)&g_sense = ns;                 \
      } else {                                              \
        while (*(volatile unsigned*)&g_sense != ns)         \
          __nanosleep(20);                                  \
      }                                                     \
      __threadfence();                                      \
      s_sense = ns;                                         \
    }                                                       \
    __syncthreads();                                        \
  } while (0)

  GBAR();  // zero-init visible everywhere

  const int bt = tid & 31;       // 4 batch elems: b = 4*bt..4*bt+3
  const int s = tid >> 5;        // k sub-slice (16 k each)
  const int s16 = s * 16;

  for (int t = 0; t < Tt; ++t) {
    const int cur = t & 1, prv = cur ^ 1;
    const float* h0p = g_h0[prv];
    float* h0c = g_h0[cur];
    const float* h1p = g_h1[prv];
    float* h1c = g_h1[cur];

    if (tid < Bt) srcsh[tid] = src[tid * Tt + t];

    // ============ phase 1: partial = h0_prev[kslice] @ Whh0 ============
    {
      ull acc0[16], acc1[16];
#pragma unroll
      for (int c = 0; c < 16; ++c) { acc0[c] = 0ull; acc1[c] = 0ull; }
      const float4* hp = (const float4*)(h0p + (size_t)kbase * Bt);
#pragma unroll 4
      for (int kk = 0; kk < 16; ++kk) {
        int k = s16 + kk;
        float4 hv = hp[k * 32 + bt];
        ull h01 = pk(hv.x, hv.y), h23 = pk(hv.z, hv.w);
        const ull* wr = Wp0 + k * 16;
#pragma unroll
        for (int c = 0; c < 16; ++c) {
          acc0[c] = fma2(wr[c], h01, acc0[c]);
          acc1[c] = fma2(wr[c], h23, acc1[c]);
        }
      }
#pragma unroll
      for (int c = 0; c < 16; ++c) {
        red2[(s16 + c) * 64 + 2 * bt] = acc0[c];
        red2[(s16 + c) * 64 + 2 * bt + 1] = acc1[c];
      }
    }
    __syncthreads();
#pragma unroll
    for (int i = 0; i < 4; ++i) {
      int o = tid + i * 256;
      int c = o >> 6, pr = o & 63;
      ull sm = red2[c * 64 + pr];
#pragma unroll
      for (int s2 = 1; s2 < 8; ++s2) sm = add2(sm, red2[s2 * 1024 + c * 64 + pr]);
      st_mail(mail_base, c >> 2, rank * 256 + (c & 3) * 64 + pr, sm);
    }
    CSYNC();
    {
      int jj = tid >> 6, pr = tid & 63, b0 = pr * 2;
      ull sm = add2(add2(mail2[jj * 64 + pr], mail2[256 + jj * 64 + pr]),
                    add2(mail2[512 + jj * 64 + pr], mail2[768 + jj * 64 + pr]));
      float2 v = upk(sm);
      v.x += Psh[srcsh[b0] * 4 + jj];
      v.y += Psh[srcsh[b0 + 1] * 4 + jj];
      float2 prev = *(const float2*)&h0p[(j0 + jj) * Bt + b0];
      float2 nv;
      nv.x = (t < lensh[b0]) ? tanhf(v.x) : prev.x;
      nv.y = (t < lensh[b0 + 1]) ? tanhf(v.y) : prev.y;
      *(float2*)&h0c[(j0 + jj) * Bt + b0] = nv;
    }
    GBAR();  // h0(t) visible, mailbox reads done everywhere

    // ============ phase 2: partial = h0(t)@Wxh1 + h1_prev@Whh1 ============
    {
      ull acc0[16], acc1[16];
#pragma unroll
      for (int c = 0; c < 16; ++c) { acc0[c] = 0ull; acc1[c] = 0ull; }
      const float4* hpA = (const float4*)(h0c + (size_t)kbase * Bt);
      const float4* hpB = (const float4*)(h1p + (size_t)kbase * Bt);
#pragma unroll 2
      for (int kk = 0; kk < 16; ++kk) {
        int k = s16 + kk;
        float4 ha = hpA[k * 32 + bt];
        float4 hb = hpB[k * 32 + bt];
        ull a01 = pk(ha.x, ha.y), a23 = pk(ha.z, ha.w);
        ull b01 = pk(hb.x, hb.y), b23 = pk(hb.z, hb.w);
        const ull* wrA = Wp1 + k * 16;
        const ull* wrB = Wp2 + k * 16;
#pragma unroll
        for (int c = 0; c < 16; ++c) {
          acc0[c] = fma2(wrA[c], a01, acc0[c]);
          acc1[c] = fma2(wrA[c], a23, acc1[c]);
          acc0[c] = fma2(wrB[c], b01, acc0[c]);
          acc1[c] = fma2(wrB[c], b23, acc1[c]);
        }
      }
#pragma unroll
      for (int c = 0; c < 16; ++c) {
        red2[(s16 + c) * 64 + 2 * bt] = acc0[c];
        red2[(s16 + c) * 64 + 2 * bt + 1] = acc1[c];
      }
    }
    __syncthreads();
#pragma unroll
    for (int i = 0; i < 4; ++i) {
      int o = tid + i * 256;
      int c = o >> 6, pr = o & 63;
      ull sm = red2[c * 64 + pr];
#pragma unroll
      for (int s2 = 1; s2 < 8; ++s2) sm = add2(sm, red2[s2 * 1024 + c * 64 + pr]);
      st_mail(mail_base, c >> 2, rank * 256 + (c & 3) * 64 + pr, sm);
    }
    CSYNC();
    {
      int jj = tid >> 6, pr = tid & 63, b0 = pr * 2;
      ull sm = add2(add2(mail2[jj * 64 + pr], mail2[256 + jj * 64 + pr]),
                    add2(mail2[512 + jj * 64 + pr], mail2[768 + jj * 64 + pr]));
      float2 v = upk(sm);
      float bv = bsh[jj];
      v.x += bv;
      v.y += bv;
      float2 prev = *(const float2*)&h1p[(j0 + jj) * Bt + b0];
      float2 nv;
      nv.x = (t < lensh[b0]) ? tanhf(v.x) : prev.x;
      nv.y = (t < lensh[b0 + 1]) ? tanhf(v.y) : prev.y;
      *(float2*)&h1c[(j0 + jj) * Bt + b0] = nv;
      float* ys = g_ysT + (size_t)t * (Ht * Bt);
      *(float2*)&ys[(j0 + jj) * Bt + b0] = nv;
    }
    GBAR();  // h1(t), ys(t) visible; mailbox free for next step
  }
#undef GBAR
  CSYNC();
}

// ---------------- kernel 3: logits = ys @ fc_w + fc_b ----------------
__global__ __launch_bounds__(256) void fc_kernel(const float* __restrict__ fcw,
                                                 const float* __restrict__ fcb,
                                                 float* __restrict__ out) {
  __shared__ float4 Ash[32 * 32];
  __shared__ float4 Bsh[32 * 16];
  const int t = blockIdx.y;
  const int pt = blockIdx.x;
  const int tid = threadIdx.x;
  const int pq = tid & 15;
  const int bq = tid >> 4;
  const float4* ys4 = (const float4*)g_ysT + (size_t)t * (Ht * Bt / 4);
  const float4* w4 = (const float4*)fcw;

  float4 acc[8];
#pragma unroll
  for (int i = 0; i < 8; ++i) acc[i] = make_float4(0, 0, 0, 0);

  for (int k0 = 0; k0 < Ht; k0 += 32) {
#pragma unroll
    for (int i = 0; i < 4; ++i) {
      int idx = tid + i * 256;
      int kk = idx >> 5, b4 = idx & 31;
      Ash[idx] = ys4[(k0 + kk) * 32 + b4];
    }
#pragma unroll
    for (int i = 0; i < 2; ++i) {
      int idx = tid + i * 256;
      int kk = idx >> 4, p4 = idx & 15;
      Bsh[idx] = w4[(k0 + kk) * (VPt / 4) + pt * 16 + p4];
    }
    __syncthreads();
#pragma unroll
    for (int kk = 0; kk < 32; ++kk) {
      float4 wv = Bsh[kk * 16 + pq];
      float4 hA = Ash[kk * 32 + bq * 2];
      float4 hB = Ash[kk * 32 + bq * 2 + 1];
      float hb[8] = {hA.x, hA.y, hA.z, hA.w, hB.x, hB.y, hB.z, hB.w};
#pragma unroll
      for (int i = 0; i < 8; ++i) {
        acc[i].x = fmaf(hb[i], wv.x, acc[i].x);
        acc[i].y = fmaf(hb[i], wv.y, acc[i].y);
        acc[i].z = fmaf(hb[i], wv.z, acc[i].z);
        acc[i].w = fmaf(hb[i], wv.w, acc[i].w);
      }
    }
    __syncthreads();
  }
  float4 bv = ((const float4*)fcb)[pt * 16 + pq];
  float4* out4 = (float4*)out;
#pragma unroll
  for (int i = 0; i < 8; ++i) {
    int b = bq * 8 + i;
    float4 v;
    v.x = acc[i].x + bv.x;
    v.y = acc[i].y + bv.y;
    v.z = acc[i].z + bv.z;
    v.w = acc[i].w + bv.w;
    out4[((size_t)b * Tt + t) * (VPt / 4) + pt * 16 + pq] = v;
  }
}

extern "C" void kernel_launch(void* const* d_in, const int* in_sizes, int n_in,
                              void* d_out, int out_size) {
  const int* src = (const int*)d_in[0];
  const int* lens = (const int*)d_in[1];
  const float* emb = (const float*)d_in[2];
  const float* Wxh0 = (const float*)d_in[3];
  const float* bxh0 = (const float*)d_in[4];
  const float* Whh0 = (const float*)d_in[5];
  const float* Wxh1 = (const float*)d_in[6];
  const float* bxh1 = (const float*)d_in[7];
  const float* Whh1 = (const float*)d_in[8];
  const float* fcw = (const float*)d_in[9];
  const float* fcb = (const float*)d_in[10];

  const int smem_bytes = 3 * 16384 + 65536 + 8192 + 1024;  // 123904
  cudaFuncSetAttribute(rec_kernel, cudaFuncAttributeMaxDynamicSharedMemorySize,
                       smem_bytes);

  proj_kernel<<<dim3(VCt, 4), 128>>>(emb, Wxh0, bxh0);
  rec_kernel<<<NCTA, 256, smem_bytes>>>(src, lens, Whh0, Wxh1, bxh1, Whh1);
  fc_kernel<<<dim3(2, Tt), 256>>>(fcw, fcb, (float*)d_out);
}